// round 17
// baseline (speedup 1.0000x reference)
#include <cuda_runtime.h>
#include <cuda_fp16.h>
#include <math.h>
#include <stdint.h>

// ---------------- problem constants ----------------
#define B   2
#define S   1024
#define H   4096
#define NH  32
#define NKV 8
#define D   128
#define GROUPS (NH / NKV)   // 4
#define EPS 1e-6f
#define QSCALE 0.08838834764831845f   // 1/sqrt(128)
#define MSEQ (B * S)        // 2048 rows
#define NQKV ((NH + 2 * NKV) * D)   // 6144
#define LOG2E 1.4426950408889634f
#define PBIAS  12.0f                 // P scaled by 2^12 (cancels in O/l)

// ---------------- scratch (device globals, fp16) ----------------
__device__ __align__(16) __half g_xh [MSEQ * H];       // hidden fp16
__device__ __align__(16) __half g_wh [NQKV * H];       // stacked Wq|Wk|Wv
__device__ __align__(16) __half g_woh[H * NH * D];     // Wo
__device__ __align__(16) __half g_aoh[MSEQ * NH * D];  // attn out fp16
// flash inputs: q (pre-scaled by QSCALE), k row-major, v row-major
__device__ __align__(16) __half g_qh [B * NH  * S * D];
__device__ __align__(16) __half g_kh [B * NKV * S * D];
__device__ __align__(16) __half g_vrow[B * NKV * S * D];   // [B,NKV,S,D]

// ---------------- small helpers ----------------
__device__ __forceinline__ void cp16(uint32_t dst, const void* src) {
    asm volatile("cp.async.cg.shared.global [%0], [%1], 16;" :: "r"(dst), "l"(src) : "memory");
}
__device__ __forceinline__ void ldsm4(uint32_t addr, uint32_t& r0, uint32_t& r1,
                                      uint32_t& r2, uint32_t& r3) {
    asm volatile("ldmatrix.sync.aligned.m8n8.x4.shared.b16 {%0,%1,%2,%3}, [%4];"
        : "=r"(r0), "=r"(r1), "=r"(r2), "=r"(r3) : "r"(addr));
}
__device__ __forceinline__ void ldsm4t(uint32_t addr, uint32_t& r0, uint32_t& r1,
                                       uint32_t& r2, uint32_t& r3) {
    asm volatile("ldmatrix.sync.aligned.m8n8.x4.trans.shared.b16 {%0,%1,%2,%3}, [%4];"
        : "=r"(r0), "=r"(r1), "=r"(r2), "=r"(r3) : "r"(addr));
}
__device__ __forceinline__ void mma16816(float* c, const uint32_t* a,
                                         uint32_t b0, uint32_t b1) {
    asm volatile("mma.sync.aligned.m16n8k16.row.col.f32.f16.f16.f32 "
        "{%0,%1,%2,%3}, {%4,%5,%6,%7}, {%8,%9}, {%0,%1,%2,%3};"
        : "+f"(c[0]), "+f"(c[1]), "+f"(c[2]), "+f"(c[3])
        : "r"(a[0]), "r"(a[1]), "r"(a[2]), "r"(a[3]), "r"(b0), "r"(b1));
}

// ============================================================================
// all conversions in ONE launch
// ============================================================================
#define N4X (MSEQ * H / 4)
#define N4Q (NH * D * H / 4)
#define N4K (NKV * D * H / 4)
#define N4ALL (N4X + N4Q + 2 * N4K + N4Q)

__global__ void __launch_bounds__(256) cvt_all(
    const float* __restrict__ hidden,
    const float* __restrict__ Wq, const float* __restrict__ Wk,
    const float* __restrict__ Wv, const float* __restrict__ Wo)
{
    int i = blockIdx.x * 256 + threadIdx.x;
    if (i >= N4ALL) return;
    const float* src;
    __half* dst;
    int j = i;
    if (j < N4X)                { src = hidden; dst = g_xh; }
    else if ((j -= N4X) < N4Q)  { src = Wq; dst = g_wh; }
    else if ((j -= N4Q) < N4K)  { src = Wk; dst = g_wh + (size_t)NH * D * H; }
    else if ((j -= N4K) < N4K)  { src = Wv; dst = g_wh + (size_t)(NH + NKV) * D * H; }
    else { j -= N4K;              src = Wo; dst = g_woh; }
    float4 x = ((const float4*)src)[j];
    ((__half2*)dst)[2 * j]     = __floats2half2_rn(x.x, x.y);
    ((__half2*)dst)[2 * j + 1] = __floats2half2_rn(x.z, x.w);
}

// ============================================================================
// mma.sync fp16 NT GEMM (1 term): C[M,N] = A[M,K]*B[N,K]^T.
// Block tile 128x128, K-tile 64, 8 warps (4m x 2n), warp tile 32x64.
// 3-stage cp.async ring, ONE __syncthreads per K-tile, 2 CTAs/SM.
// FUSED=true (QKV): one N-tile == one head; epilogue does RMSNorm+RoPE.
// ============================================================================
#define ROWB 144                       // bytes per 64-fp16 row (128 + 16 pad)
#define MATB (128 * ROWB)              // 18432 per matrix tile
#define STGB (2 * MATB)                // A|B per stage = 36864
#define GSMEM_PIPE (3 * STGB)          // 110592
#define EPI_PITCH 132
#define GSMEM_QKV  GSMEM_PIPE
#define GSMEM_O    GSMEM_PIPE

template<bool FUSED>
__global__ void __launch_bounds__(256, 2) gemm_mma(
    const __half* __restrict__ A, const __half* __restrict__ Bm,
    float* __restrict__ C, int M, int N, int K,
    const float* __restrict__ cosb, const float* __restrict__ sinb,
    const float* __restrict__ qw,   const float* __restrict__ kw)
{
    extern __shared__ __align__(128) char smem[];
    const uint32_t sbase = (uint32_t)__cvta_generic_to_shared(smem);
    const int tid  = threadIdx.x;
    const int lane = tid & 31;
    const int wid  = tid >> 5;
    const int warp_m = wid >> 1;
    const int warp_n = wid & 1;
    const int m0 = blockIdx.y * 128;
    const int n0 = blockIdx.x * 128;
    const int KT = K >> 6;         // K / 64

    float acc[2][8][4];
#pragma unroll
    for (int i = 0; i < 2; i++)
#pragma unroll
        for (int j = 0; j < 8; j++)
#pragma unroll
            for (int q = 0; q < 4; q++) acc[i][j][q] = 0.f;

    auto fill = [&](int s, int kt) {
        const uint32_t st = sbase + s * STGB;
#pragma unroll
        for (int i = 0; i < 8; i++) {
            const int v = ((i & 3) << 8) + tid;     // 0..1023 within matrix
            const int r = v >> 3, c = v & 7;
            const __half* gb = (i < 4) ? A : Bm;
            const int grow = ((i < 4) ? m0 : n0) + r;
            cp16(st + (i >> 2) * MATB + r * ROWB + c * 16,
                 gb + (size_t)grow * K + (size_t)kt * 64 + c * 8);
        }
        asm volatile("cp.async.commit_group;" ::: "memory");
    };

    fill(0, 0); fill(1, 1); fill(2, 2);

    const uint32_t aOff = (uint32_t)((warp_m * 32 + (lane & 15)) * ROWB + ((lane >> 4) << 4));
    const uint32_t bOff = (uint32_t)(MATB + (warp_n * 64 + (lane & 15)) * ROWB + ((lane >> 4) << 4));

    for (int kt = 0; kt < KT; kt++) {
        asm volatile("cp.async.wait_group 1;" ::: "memory");
        __syncthreads();
        if (kt >= 1) {
            const int t = kt + 2;
            if (t < KT) fill(t % 3, t);
            else asm volatile("cp.async.commit_group;" ::: "memory");
        }

        const uint32_t st = sbase + (kt % 3) * STGB;
#pragma unroll
        for (int k16 = 0; k16 < 4; k16++) {
            const uint32_t ko = k16 * 32;
            uint32_t a[2][4], bh[4][4];
#pragma unroll
            for (int mi = 0; mi < 2; mi++)
                ldsm4(st + aOff + mi * (16 * ROWB) + ko,
                      a[mi][0], a[mi][1], a[mi][2], a[mi][3]);
#pragma unroll
            for (int ni = 0; ni < 4; ni++)
                ldsm4(st + bOff + ni * (16 * ROWB) + ko,
                      bh[ni][0], bh[ni][1], bh[ni][2], bh[ni][3]);
#pragma unroll
            for (int mi = 0; mi < 2; mi++)
#pragma unroll
                for (int ni = 0; ni < 4; ni++) {
                    mma16816(acc[mi][ni * 2],     a[mi], bh[ni][0], bh[ni][2]);
                    mma16816(acc[mi][ni * 2 + 1], a[mi], bh[ni][1], bh[ni][3]);
                }
        }
    }

    if (!FUSED) {
#pragma unroll
        for (int mi = 0; mi < 2; mi++) {
            const int row = m0 + warp_m * 32 + mi * 16 + (lane >> 2);
#pragma unroll
            for (int nj = 0; nj < 8; nj++) {
                const int col = n0 + warp_n * 64 + nj * 8 + (lane & 3) * 2;
                *(float2*)(C + (size_t)row * N + col) =
                    make_float2(acc[mi][nj][0], acc[mi][nj][1]);
                *(float2*)(C + (size_t)(row + 8) * N + col) =
                    make_float2(acc[mi][nj][2], acc[mi][nj][3]);
            }
        }
        return;
    }

    // ---- fused QKV epilogue: this N-tile is one head (hs = n0/128) ----
    asm volatile("cp.async.wait_group 0;" ::: "memory");
    __syncthreads();   // pipeline smem now free for staging

    const int hs = n0 >> 7;
    const int rbase = warp_m * 32 + (lane >> 2);

    if (hs >= NH + NKV) {
        const int vh = hs - NH - NKV;
#pragma unroll
        for (int mi = 0; mi < 2; mi++) {
            const int rl = rbase + mi * 16;
#pragma unroll
            for (int nj = 0; nj < 8; nj++) {
                const int d = warp_n * 64 + nj * 8 + (lane & 3) * 2;
                const int bs0 = m0 + rl, bs1 = bs0 + 8;
                const size_t i0 = (((size_t)(bs0 >> 10) * NKV + vh) * S + (bs0 & 1023)) * D + d;
                const size_t i1 = (((size_t)(bs1 >> 10) * NKV + vh) * S + (bs1 & 1023)) * D + d;
                *(__half2*)(g_vrow + i0) = __floats2half2_rn(acc[mi][nj][0], acc[mi][nj][1]);
                *(__half2*)(g_vrow + i1) = __floats2half2_rn(acc[mi][nj][2], acc[mi][nj][3]);
            }
        }
        return;
    }

    const bool isQ = (hs < NH);
    float* sst  = (float*)smem;
    float* ssum = sst + 128 * EPI_PITCH;

#pragma unroll
    for (int mi = 0; mi < 2; mi++) {
        float s0 = 0.f, s1 = 0.f;
#pragma unroll
        for (int nj = 0; nj < 8; nj++) {
            s0 += acc[mi][nj][0] * acc[mi][nj][0] + acc[mi][nj][1] * acc[mi][nj][1];
            s1 += acc[mi][nj][2] * acc[mi][nj][2] + acc[mi][nj][3] * acc[mi][nj][3];
        }
        s0 += __shfl_xor_sync(0xffffffffu, s0, 1);
        s0 += __shfl_xor_sync(0xffffffffu, s0, 2);
        s1 += __shfl_xor_sync(0xffffffffu, s1, 1);
        s1 += __shfl_xor_sync(0xffffffffu, s1, 2);
        if ((lane & 3) == 0) {
            ssum[(rbase + mi * 16) * 2 + warp_n]     = s0;
            ssum[(rbase + mi * 16 + 8) * 2 + warp_n] = s1;
        }
    }
    __syncthreads();

    const float* wp = isQ ? qw : kw;
#pragma unroll
    for (int mi = 0; mi < 2; mi++) {
        const int r0 = rbase + mi * 16, r1 = r0 + 8;
        const float inv0 = rsqrtf((ssum[r0 * 2] + ssum[r0 * 2 + 1]) * (1.0f / D) + EPS);
        const float inv1 = rsqrtf((ssum[r1 * 2] + ssum[r1 * 2 + 1]) * (1.0f / D) + EPS);
#pragma unroll
        for (int nj = 0; nj < 8; nj++) {
            const int d = warp_n * 64 + nj * 8 + (lane & 3) * 2;
            const float2 w2 = *(const float2*)(wp + d);
            sst[r0 * EPI_PITCH + d]     = acc[mi][nj][0] * inv0 * w2.x;
            sst[r0 * EPI_PITCH + d + 1] = acc[mi][nj][1] * inv0 * w2.y;
            sst[r1 * EPI_PITCH + d]     = acc[mi][nj][2] * inv1 * w2.x;
            sst[r1 * EPI_PITCH + d + 1] = acc[mi][nj][3] * inv1 * w2.y;
        }
    }
    __syncthreads();

    const float oscale = isQ ? QSCALE : 1.0f;
#pragma unroll
    for (int mi = 0; mi < 2; mi++) {
        const int rl0 = rbase + mi * 16;
#pragma unroll
        for (int half = 0; half < 2; half++) {
            const int rl = rl0 + half * 8;
            const int bs = m0 + rl;
            const int b  = bs >> 10, s = bs & 1023;
#pragma unroll
            for (int nj = 0; nj < 8; nj++) {
                const int d = warp_n * 64 + nj * 8 + (lane & 3) * 2;
                const float2 c2 = *(const float2*)(cosb + (size_t)bs * D + d);
                const float2 s2 = *(const float2*)(sinb + (size_t)bs * D + d);
                const float v0 = sst[rl * EPI_PITCH + d];
                const float v1 = sst[rl * EPI_PITCH + d + 1];
                const float p0 = sst[rl * EPI_PITCH + (d ^ 64)];
                const float p1 = sst[rl * EPI_PITCH + (d ^ 64) + 1];
                const float sgn = (d < 64) ? -1.f : 1.f;
                const float o0 = (v0 * c2.x + sgn * p0 * s2.x) * oscale;
                const float o1 = (v1 * c2.y + sgn * p1 * s2.y) * oscale;
                if (isQ) {
                    const size_t ix = (((size_t)b * NH + hs) * S + s) * D + d;
                    *(__half2*)(g_qh + ix) = __floats2half2_rn(o0, o1);
                } else {
                    const size_t ix = (((size_t)b * NKV + (hs - NH)) * S + s) * D + d;
                    *(__half2*)(g_kh + ix) = __floats2half2_rn(o0, o1);
                }
            }
        }
    }
}

// ============================================================================
// Causal flash attention: BM=128, BN=128, Q in REGISTERS, 3-stage KV ring.
// 1-term QK (scale pre-folded into q), 1-term PV, V via ldmatrix.trans.
// 8 warps, single __syncthreads per iteration.
// ============================================================================
#define QROW 272                       // 128 fp16 + 8 pad
#define VH_SOFF (128 * QROW)           // V within stage (34816)
#define KSTG    (2 * 128 * QROW)       // 69632
#define FSMEM   (3 * KSTG)             // 208896

__global__ void __launch_bounds__(256) flash_mma()
{
    extern __shared__ __align__(128) char fsm[];
    const uint32_t sb = (uint32_t)__cvta_generic_to_shared(fsm);
    const int tid = threadIdx.x, lane = tid & 31, wid = tid >> 5;
    const int qt = (int)gridDim.x - 1 - (int)blockIdx.x;   // heavy CTAs first
    const int bh = blockIdx.y;
    const int b = bh / NH, h = bh - b * NH;
    const int kvh = h / GROUPS;

    const __half* Qhp = g_qh + (((size_t)b * NH + h) * S + (size_t)qt * 128) * D;
    const __half* Khp = g_kh + ((size_t)b * NKV + kvh) * S * D;
    const __half* Vhp = g_vrow + ((size_t)b * NKV + kvh) * S * D;

    // ---- stage Q through slot-0 smem, hoist to registers ----
#pragma unroll
    for (int i = tid; i < 2048; i += 256) {
        const int r = i >> 4, c = i & 15;
        cp16(sb + r * QROW + c * 16, Qhp + r * D + c * 8);
    }
    asm volatile("cp.async.commit_group;" ::: "memory");
    asm volatile("cp.async.wait_group 0;" ::: "memory");
    __syncthreads();

    const uint32_t aQ = (uint32_t)((wid * 16 + (lane & 15)) * QROW + ((lane >> 4) << 4));
    uint32_t qf[8][4];
#pragma unroll
    for (int ks = 0; ks < 8; ks++)
        ldsm4(sb + aQ + ks * 32, qf[ks][0], qf[ks][1], qf[ks][2], qf[ks][3]);
    __syncthreads();   // all warps done reading Q from slot 0

    auto fillkv = [&](int slot, int kt) {
        const uint32_t st = sb + slot * KSTG;
        const __half* kh_ = Khp + (size_t)kt * 128 * D;
        const __half* vh_ = Vhp + (size_t)kt * 128 * D;
#pragma unroll
        for (int i = tid; i < 2048; i += 256) {
            const int r = i >> 4, c = i & 15;
            cp16(st + r * QROW + c * 16,           kh_ + r * D + c * 8);
            cp16(st + VH_SOFF + r * QROW + c * 16, vh_ + r * D + c * 8);
        }
        asm volatile("cp.async.commit_group;" ::: "memory");
    };

    // prologue: 3 stages (empty commits keep group arithmetic valid)
#pragma unroll
    for (int i = 0; i < 3; i++) {
        if (i <= qt) fillkv(i, i);
        else asm volatile("cp.async.commit_group;" ::: "memory");
    }

    float m0 = -INFINITY, m1 = -INFINITY, l0 = 0.f, l1 = 0.f;
    float o[16][4];
#pragma unroll
    for (int f = 0; f < 16; f++)
#pragma unroll
        for (int e = 0; e < 4; e++) o[f][e] = 0.f;

    const uint32_t bK = (uint32_t)((lane & 15) * QROW + ((lane >> 4) << 4));

    for (int kt = 0; kt <= qt; kt++) {
        asm volatile("cp.async.wait_group 1;" ::: "memory");
        __syncthreads();
        if (kt >= 1) {
            const int t = kt + 2;
            if (t <= qt) fillkv(t % 3, t);
            else asm volatile("cp.async.commit_group;" ::: "memory");
        }
        const uint32_t st = sb + (kt % 3) * KSTG;

        // ---- scores: 1-term QK over 128 cols (Q from registers) ----
        float s[16][4];
#pragma unroll
        for (int f = 0; f < 16; f++)
#pragma unroll
            for (int e = 0; e < 4; e++) s[f][e] = 0.f;

#pragma unroll
        for (int ks = 0; ks < 8; ks++) {
            const uint32_t ko = ks * 32;
#pragma unroll
            for (int nb = 0; nb < 8; nb++) {
                uint32_t k0, k1, k2, k3;
                ldsm4(st + bK + nb * (16 * QROW) + ko, k0, k1, k2, k3);
                mma16816(s[nb * 2],     qf[ks], k0, k2);
                mma16816(s[nb * 2 + 1], qf[ks], k1, k3);
            }
        }

        // ---- causal mask (diagonal tile only) ----
        if (kt == qt) {
            const int r0 = qt * 128 + wid * 16 + (lane >> 2);
            const int r1 = r0 + 8;
#pragma unroll
            for (int f = 0; f < 16; f++) {
                const int c0 = kt * 128 + f * 8 + (lane & 3) * 2;
                if (c0     > r0) s[f][0] = -INFINITY;
                if (c0 + 1 > r0) s[f][1] = -INFINITY;
                if (c0     > r1) s[f][2] = -INFINITY;
                if (c0 + 1 > r1) s[f][3] = -INFINITY;
            }
        }

        // ---- online softmax over 128 cols ----
        float a0 = -INFINITY, a1 = -INFINITY;
#pragma unroll
        for (int f = 0; f < 16; f++) {
            a0 = fmaxf(a0, fmaxf(s[f][0], s[f][1]));
            a1 = fmaxf(a1, fmaxf(s[f][2], s[f][3]));
        }
        a0 = fmaxf(a0, __shfl_xor_sync(0xffffffffu, a0, 1));
        a0 = fmaxf(a0, __shfl_xor_sync(0xffffffffu, a0, 2));
        a1 = fmaxf(a1, __shfl_xor_sync(0xffffffffu, a1, 1));
        a1 = fmaxf(a1, __shfl_xor_sync(0xffffffffu, a1, 2));
        const float mn0 = fmaxf(m0, a0), mn1 = fmaxf(m1, a1);
        const float sc0 = exp2f((m0 - mn0) * LOG2E);
        const float sc1 = exp2f((m1 - mn1) * LOG2E);
        float rs0 = 0.f, rs1 = 0.f;
#pragma unroll
        for (int f = 0; f < 16; f++) {
            s[f][0] = exp2f((s[f][0] - mn0) * LOG2E + PBIAS);
            s[f][1] = exp2f((s[f][1] - mn0) * LOG2E + PBIAS);
            s[f][2] = exp2f((s[f][2] - mn1) * LOG2E + PBIAS);
            s[f][3] = exp2f((s[f][3] - mn1) * LOG2E + PBIAS);
            rs0 += s[f][0] + s[f][1];
            rs1 += s[f][2] + s[f][3];
        }
        rs0 += __shfl_xor_sync(0xffffffffu, rs0, 1);
        rs0 += __shfl_xor_sync(0xffffffffu, rs0, 2);
        rs1 += __shfl_xor_sync(0xffffffffu, rs1, 1);
        rs1 += __shfl_xor_sync(0xffffffffu, rs1, 2);
        m0 = mn0; m1 = mn1;
        l0 = l0 * sc0 + rs0;
        l1 = l1 * sc1 + rs1;
#pragma unroll
        for (int f = 0; f < 16; f++) {
            o[f][0] *= sc0; o[f][1] *= sc0;
            o[f][2] *= sc1; o[f][3] *= sc1;
        }

        // ---- pack P to fp16 A-frags ----
        uint32_t ph[8][4];
#pragma unroll
        for (int kb = 0; kb < 8; kb++) {
            __half2 t;
            t = __floats2half2_rn(s[2 * kb][0],     s[2 * kb][1]);     ph[kb][0] = *(uint32_t*)&t;
            t = __floats2half2_rn(s[2 * kb][2],     s[2 * kb][3]);     ph[kb][1] = *(uint32_t*)&t;
            t = __floats2half2_rn(s[2 * kb + 1][0], s[2 * kb + 1][1]); ph[kb][2] = *(uint32_t*)&t;
            t = __floats2half2_rn(s[2 * kb + 1][2], s[2 * kb + 1][3]); ph[kb][3] = *(uint32_t*)&t;
        }

        // ---- PV: 1-term, row-major V via ldmatrix.trans ----
#pragma unroll
        for (int kb = 0; kb < 8; kb++) {
#pragma unroll
            for (int dp = 0; dp < 8; dp++) {
                uint32_t v0, v1, v2, v3;
                ldsm4t(st + VH_SOFF + bK + kb * (16 * QROW) + dp * 32, v0, v1, v2, v3);
                mma16816(o[dp * 2],     ph[kb], v0, v1);
                mma16816(o[dp * 2 + 1], ph[kb], v2, v3);
            }
        }
    }

    // ---- epilogue: O/l, single fp16 for 1-term O-projection ----
    const float i0 = 1.f / l0, i1 = 1.f / l1;
    const int gr0 = qt * 128 + wid * 16 + (lane >> 2);
#pragma unroll
    for (int f = 0; f < 16; f++) {
        const int d0 = f * 8 + (lane & 3) * 2;
        const size_t ix0 = ((size_t)(b * S + gr0) * NH + h) * D + d0;
        const size_t ix1 = ((size_t)(b * S + gr0 + 8) * NH + h) * D + d0;
        __half2 h0 = __floats2half2_rn(o[f][0] * i0, o[f][1] * i0);
        __half2 h1 = __floats2half2_rn(o[f][2] * i1, o[f][3] * i1);
        *(__half2*)(g_aoh + ix0) = h0;
        *(__half2*)(g_aoh + ix1) = h1;
    }
}

// ============================================================================
// host launcher
// ============================================================================
extern "C" void kernel_launch(void* const* d_in, const int* in_sizes, int n_in,
                              void* d_out, int out_size)
{
    const float* hidden = (const float*)d_in[0];
    const float* cosb   = (const float*)d_in[1];
    const float* sinb   = (const float*)d_in[2];
    const float* Wq     = (const float*)d_in[3];
    const float* Wk     = (const float*)d_in[4];
    const float* Wv     = (const float*)d_in[5];
    const float* Wo     = (const float*)d_in[6];
    const float* qw     = (const float*)d_in[7];
    const float* kw     = (const float*)d_in[8];
    float* out = (float*)d_out;

    __half *xh, *wh, *woh, *aoh;
    cudaGetSymbolAddress((void**)&xh,  g_xh);
    cudaGetSymbolAddress((void**)&wh,  g_wh);
    cudaGetSymbolAddress((void**)&woh, g_woh);
    cudaGetSymbolAddress((void**)&aoh, g_aoh);

    cudaFuncSetAttribute(gemm_mma<true>,  cudaFuncAttributeMaxDynamicSharedMemorySize, GSMEM_QKV);
    cudaFuncSetAttribute(gemm_mma<false>, cudaFuncAttributeMaxDynamicSharedMemorySize, GSMEM_O);
    cudaFuncSetAttribute(flash_mma, cudaFuncAttributeMaxDynamicSharedMemorySize, FSMEM);

    // all conversions in one launch
    cvt_all<<<(N4ALL + 255) / 256, 256>>>(hidden, Wq, Wk, Wv, Wo);

    // fused QKV projection + RMSNorm + RoPE -> g_qh / g_kh / g_vrow
    gemm_mma<true><<<dim3(NQKV / 128, MSEQ / 128), 256, GSMEM_QKV>>>(
        xh, wh, nullptr, MSEQ, NQKV, H, cosb, sinb, qw, kw);

    // causal flash attention (BM=BN=128, Q in registers, 3-stage KV)
    flash_mma<<<dim3(S / 128, B * NH), 256, FSMEM>>>();

    // output projection (fp32 out): [2048, 4096] = AO * Wo^T
    gemm_mma<false><<<dim3(H / 128, MSEQ / 128), 256, GSMEM_O>>>(
        aoh, woh, out, MSEQ, H, NH * D, nullptr, nullptr, nullptr, nullptr);
}